// round 16
// baseline (speedup 1.0000x reference)
#include <cuda_runtime.h>
#include <math.h>
#include <stdint.h>

// CGGRLoss, R16: R15 (171.3us) + PDL overlap. The finalize kernel launches
// with programmatic stream serialization: its launch/ramp overlaps the row
// kernel's tail; griddepcontrol.wait provides the data dependency. Row CTAs
// signal launch_dependents after publishing their stats.

#define MAXN 8192
#define LOG2E 1.4426950408889634f

static __device__ float g_ce[MAXN];
static __device__ float g_part[MAXN];              // ent_norm + 1 - margin
static __device__ unsigned g_maxce_key;            // order-preserving key of max ce (init 0)
static __device__ unsigned long long g_sumconf_fx; // sum of conf * 2^32 (init 0)

__device__ __forceinline__ float ex2f(float x) {
    float y;
    asm("ex2.approx.ftz.f32 %0, %1;" : "=f"(y) : "f"(x));
    return y;   // ex2(-inf) = +0, ex2(0) = 1 exactly
}

// order-preserving float<->u32 maps (ascending float == ascending uint)
__device__ __forceinline__ unsigned f2key(float f) {
    unsigned u = __float_as_uint(f);
    return (u & 0x80000000u) ? ~u : (u | 0x80000000u);
}
__device__ __forceinline__ float key2f(unsigned k) {
    unsigned u = (k & 0x80000000u) ? (k & 0x7FFFFFFFu) : ~k;
    return __uint_as_float(u);
}

struct OS { float m1, m2, s, t; };

__device__ __forceinline__ void os_merge(OS& a, const OS& b) {
    float M1 = fmaxf(a.m1, b.m1);
    float M2 = fmaxf(fminf(a.m1, b.m1), fmaxf(a.m2, b.m2));
    float sa = (a.m1 == -INFINITY) ? 0.f : __expf(a.m1 - M1);
    float sb = (b.m1 == -INFINITY) ? 0.f : __expf(b.m1 - M1);
    a.s = a.s * sa + b.s * sb;
    a.t = a.t * sa + b.t * sb;
    a.m1 = M1; a.m2 = M2;
}

// ---------------------------------------------------------------------------
// Kernel 1: one block per row, 256 threads. (streaming loop at ~6.9 TB/s cap)
// ---------------------------------------------------------------------------
__global__ void __launch_bounds__(256) row_stats_kernel(
    const float* __restrict__ lf, const int* __restrict__ tf,
    int V, float inv_logV)
{
    const int row  = blockIdx.x;
    const int tid  = threadIdx.x;
    const int lane = tid & 31;
    const float* p = lf + (size_t)row * (size_t)V;

    __shared__ OS swarp[8];
    __shared__ float s_lt;

    if (tid == 0) s_lt = __ldg(p + __ldg(tf + row));

    float m1 = -INFINITY, m2 = -INFINITY;
    float bm = -INFINITY, b2 = -INFINITY;
    float s0 = 0.f, s1 = 0.f, t0 = 0.f, t1 = 0.f;

    #define TOP2(x) { float lo_ = fminf((x), m1); m1 = fmaxf((x), m1); m2 = fmaxf(m2, lo_); }
    #define RESCALE() if (m1 > bm) { \
        float nb2_ = m1 * LOG2E; \
        float sc_  = ex2f(b2 - nb2_); \
        s0 *= sc_; s1 *= sc_; t0 *= sc_; t1 *= sc_; \
        bm = m1; b2 = nb2_; }
    #define EXP4(v) { float e_; \
        e_ = ex2f(fmaf((v).x, LOG2E, -b2)); s0 += e_; t0 = fmaf(e_, (v).x, t0); \
        e_ = ex2f(fmaf((v).y, LOG2E, -b2)); s1 += e_; t1 = fmaf(e_, (v).y, t1); \
        e_ = ex2f(fmaf((v).z, LOG2E, -b2)); s0 += e_; t0 = fmaf(e_, (v).z, t0); \
        e_ = ex2f(fmaf((v).w, LOG2E, -b2)); s1 += e_; t1 = fmaf(e_, (v).w, t1); }

    if (((V & 3) == 0) && ((((uintptr_t)p) & 15u) == 0)) {
        const int V4 = V >> 2;
        const float4* p4 = reinterpret_cast<const float4*>(p);
        const int pairs = V4 >> 9;
        int i = tid;
        if (pairs > 0) {
            float4 c0 = __ldcs(p4 + i);
            float4 c1 = __ldcs(p4 + i + 256);
            #pragma unroll 1
            for (int it = 1; it < pairs; it++) {
                int nx = i + 512;
                float4 n0 = __ldcs(p4 + nx);
                float4 n1 = __ldcs(p4 + nx + 256);
                TOP2(c0.x); TOP2(c0.y); TOP2(c0.z); TOP2(c0.w);
                TOP2(c1.x); TOP2(c1.y); TOP2(c1.z); TOP2(c1.w);
                RESCALE();
                EXP4(c0);
                EXP4(c1);
                c0 = n0; c1 = n1; i = nx;
            }
            TOP2(c0.x); TOP2(c0.y); TOP2(c0.z); TOP2(c0.w);
            TOP2(c1.x); TOP2(c1.y); TOP2(c1.z); TOP2(c1.w);
            RESCALE();
            EXP4(c0);
            EXP4(c1);
            i += 512;
        }
        for (; i < V4; i += 256) {
            float4 a = __ldcs(p4 + i);
            TOP2(a.x); TOP2(a.y); TOP2(a.z); TOP2(a.w);
            RESCALE();
            EXP4(a);
        }
    } else {
        for (int i = tid; i < V; i += 256) {
            float x = p[i];
            TOP2(x);
            RESCALE();
            float e = ex2f(fmaf(x, LOG2E, -b2));
            s0 += e; t0 = fmaf(e, x, t0);
        }
    }
    #undef TOP2
    #undef RESCALE
    #undef EXP4

    OS st;
    st.m1 = m1; st.m2 = m2; st.s = s0 + s1; st.t = t0 + t1;

    #pragma unroll
    for (int off = 16; off; off >>= 1) {
        OS o;
        o.m1 = __shfl_xor_sync(0xffffffffu, st.m1, off);
        o.m2 = __shfl_xor_sync(0xffffffffu, st.m2, off);
        o.s  = __shfl_xor_sync(0xffffffffu, st.s,  off);
        o.t  = __shfl_xor_sync(0xffffffffu, st.t,  off);
        os_merge(st, o);
    }
    if (lane == 0) swarp[tid >> 5] = st;
    __syncthreads();

    if (tid == 0) {
        #pragma unroll
        for (int w = 1; w < 8; w++) os_merge(st, swarp[w]);

        float logs = __logf(st.s);
        float logZ = st.m1 + logs;
        float ce   = logZ - s_lt;
        float ent  = logZ - st.t / st.s;
        float conf = 1.f / st.s;                    // p1, in (0, 1]
        float p2   = __expf(st.m2 - st.m1) * conf;  // p2
        float margin = conf - p2;

        g_ce[row]   = ce;
        g_part[row] = ent * inv_logV + 1.f - margin;

        atomicMax(&g_maxce_key, f2key(ce));
        unsigned long long cfx = (unsigned long long)((double)conf * 4294967296.0);
        atomicAdd(&g_sumconf_fx, cfx);

        __threadfence();   // publish before signaling dependents
        asm volatile("griddepcontrol.launch_dependents;" ::: "memory");
    }
}

// ---------------------------------------------------------------------------
// block reduction for 1024 threads (32 warps)
// ---------------------------------------------------------------------------
__device__ __forceinline__ float blk_sum32(float v, float* rbuf) {
    #pragma unroll
    for (int off = 16; off; off >>= 1)
        v += __shfl_xor_sync(0xffffffffu, v, off);
    if ((threadIdx.x & 31) == 0) rbuf[threadIdx.x >> 5] = v;
    __syncthreads();
    if (threadIdx.x < 32) {
        v = rbuf[threadIdx.x];
        #pragma unroll
        for (int off = 16; off; off >>= 1)
            v += __shfl_xor_sync(0xffffffffu, v, off);
        if (threadIdx.x == 0) rbuf[0] = v;
    }
    __syncthreads();
    float r = rbuf[0];
    __syncthreads();
    return r;
}

// warp-0 suffix-scan + winner-digit select over 256 bins. Called by tid<32.
__device__ __forceinline__ void warp0_select(
    const unsigned* hist, volatile unsigned* s_prefix, volatile int* s_rank,
    int shift)
{
    const int L = threadIdx.x;
    unsigned b[8];
    unsigned tot = 0;
    #pragma unroll
    for (int j = 0; j < 8; j++) { b[j] = hist[L * 8 + j]; tot += b[j]; }

    unsigned S = tot;
    #pragma unroll
    for (int off = 1; off < 32; off <<= 1) {
        unsigned v = __shfl_down_sync(0xffffffffu, S, off);
        if (L + off < 32) S += v;
    }
    unsigned above = S - tot;

    int r = *s_rank;
    unsigned pfx = *s_prefix;
    __syncwarp();

    unsigned run = above;
    int windig = -1; unsigned wabove = 0;
    #pragma unroll
    for (int j = 7; j >= 0; j--) {
        unsigned nrun = run + b[j];
        if ((int)nrun >= r && (int)run < r) { windig = L * 8 + j; wabove = run; }
        run = nrun;
    }
    if (windig >= 0) {
        *s_prefix = pfx | ((unsigned)windig << shift);
        *s_rank   = r - (int)wabove;
    }
}

// ---------------------------------------------------------------------------
// Kernel 2: single block, 1024 threads. PDL: ramps up concurrently with the
// row kernel, waits on the grid dependency, then runs the lean radix select.
// ---------------------------------------------------------------------------
__global__ void __launch_bounds__(1024) finalize_kernel(
    const int* __restrict__ step_ptr, float* __restrict__ out, int N)
{
    __shared__ unsigned skey[MAXN];        // 32 KB
    __shared__ float    sce[MAXN];         // 32 KB
    __shared__ unsigned hist[256];
    __shared__ float rbuf[32];
    __shared__ unsigned s_prefix;
    __shared__ int s_rank;

    const int tid  = threadIdx.x;
    const int lane = tid & 31;

    // dependency-independent setup
    if (tid < 256) hist[tid] = 0u;
    int step = *step_ptr;   // harness input, not written by row kernel

    // block until all row CTAs have signaled launch_dependents
    asm volatile("griddepcontrol.wait;" ::: "memory");

    float maxce   = key2f(g_maxce_key);
    float sumconf = (float)((double)g_sumconf_fx * (1.0 / 4294967296.0));

    if (tid == 0) {
        float progress = fminf(1.f, (float)step * (1.f / 1000.f));
        float base_rat = 1.f - progress * (1.f - 0.25f);
        float avg_conf = sumconf / (float)N;
        float ratio    = base_rat * (1.f + 0.5f * (0.5f - avg_conf) * 2.f);
        ratio = fminf(fmaxf(ratio, 0.01f), 1.f);
        int k = (int)rintf(ratio * (float)N);       // round-half-even == jnp.round
        k = min(max(k, 1), N);
        s_rank = k;
        s_prefix = 0u;
    }
    __syncthreads();

    // key build + pass-0 histogram fused
    float invm = 1.f / (maxce + 1e-6f);
    #pragma unroll 8
    for (int i = tid; i < N; i += 1024) {
        float ce = g_ce[i];
        float d  = (g_part[i] + ce * invm) * (1.f / 3.f);
        unsigned key = f2key(d);
        skey[i] = key;
        sce[i]  = ce;
        int digit = (int)(key >> 24);
        unsigned m = __match_any_sync(0xffffffffu, digit);
        int leader = __ffs(m) - 1;
        if (lane == leader)
            atomicAdd(&hist[digit], (unsigned)__popc(m));
    }
    __syncthreads();

    if (tid < 32) warp0_select(hist, &s_prefix, &s_rank, 24);
    __syncthreads();

    #pragma unroll
    for (int pass = 1; pass < 4; pass++) {
        const int shift = 24 - pass * 8;
        const unsigned himask = 0xFFFFFFFFu << (32 - pass * 8);
        if (tid < 256) hist[tid] = 0u;
        __syncthreads();
        unsigned prefix = s_prefix;

        #pragma unroll 8
        for (int i = tid; i < N; i += 1024) {
            unsigned key = skey[i];
            int digit = ((key & himask) == prefix) ? (int)((key >> shift) & 255u) : -1;
            unsigned m = __match_any_sync(0xffffffffu, digit);
            int leader = __ffs(m) - 1;
            if (lane == leader && digit >= 0)
                atomicAdd(&hist[digit], (unsigned)__popc(m));
        }
        __syncthreads();

        if (tid < 32) warp0_select(hist, &s_prefix, &s_rank, shift);
        __syncthreads();
    }
    unsigned thr_key = s_prefix;   // exact k-th largest difficulty key

    float sces = 0.f, cnt = 0.f;
    #pragma unroll 8
    for (int i = tid; i < N; i += 1024) {
        if (skey[i] >= thr_key) { sces += sce[i]; cnt += 1.f; }
    }
    sces = blk_sum32(sces, rbuf);
    cnt  = blk_sum32(cnt, rbuf);
    if (tid == 0) {
        out[0] = sces / fmaxf(cnt, 1.f);
        g_maxce_key  = 0u;          // reset for next graph replay
        g_sumconf_fx = 0ull;
    }
}

// ---------------------------------------------------------------------------
extern "C" void kernel_launch(void* const* d_in, const int* in_sizes, int n_in,
                              void* d_out, int out_size) {
    const float* lf   = (const float*)d_in[0];   // logits (B,S,V) fp32
    const int*   tf   = (const int*)d_in[1];     // targets (B,S) int32
    const int*   step = (const int*)d_in[2];     // step_count scalar int32

    int N = in_sizes[1];                 // B*S = 8192
    int V = in_sizes[0] / N;             // 32000
    if (N > MAXN) N = MAXN;

    float inv_logV = 1.f / logf((float)V);

    row_stats_kernel<<<N, 256>>>(lf, tf, V, inv_logV);

    // PDL launch: overlap finalize's launch/ramp with the row kernel's tail.
    cudaLaunchConfig_t cfg = {};
    cfg.gridDim  = dim3(1, 1, 1);
    cfg.blockDim = dim3(1024, 1, 1);
    cfg.dynamicSmemBytes = 0;
    cfg.stream = 0;
    cudaLaunchAttribute attrs[1];
    attrs[0].id = cudaLaunchAttributeProgrammaticStreamSerialization;
    attrs[0].val.programmaticStreamSerializationAllowed = 1;
    cfg.attrs = attrs;
    cfg.numAttrs = 1;
    float* outp = (float*)d_out;
    cudaError_t e = cudaLaunchKernelEx(&cfg, finalize_kernel, step, outp, N);
    if (e != cudaSuccess) {
        // fallback: plain stream-ordered launch (griddepcontrol.wait is a
        // no-op when no PDL attribute is set)
        finalize_kernel<<<1, 1024>>>(step, outp, N);
    }
}

// round 17
// speedup vs baseline: 1.0202x; 1.0202x over previous
#include <cuda_runtime.h>
#include <math.h>
#include <stdint.h>

// CGGRLoss, R16: R15 (171.3us) + PDL overlap. The finalize kernel launches
// with programmatic stream serialization: its launch/ramp overlaps the row
// kernel's tail; griddepcontrol.wait provides the data dependency. Row CTAs
// signal launch_dependents after publishing their stats.

#define MAXN 8192
#define LOG2E 1.4426950408889634f

static __device__ float g_ce[MAXN];
static __device__ float g_part[MAXN];              // ent_norm + 1 - margin
static __device__ unsigned g_maxce_key;            // order-preserving key of max ce (init 0)
static __device__ unsigned long long g_sumconf_fx; // sum of conf * 2^32 (init 0)

__device__ __forceinline__ float ex2f(float x) {
    float y;
    asm("ex2.approx.ftz.f32 %0, %1;" : "=f"(y) : "f"(x));
    return y;   // ex2(-inf) = +0, ex2(0) = 1 exactly
}

// order-preserving float<->u32 maps (ascending float == ascending uint)
__device__ __forceinline__ unsigned f2key(float f) {
    unsigned u = __float_as_uint(f);
    return (u & 0x80000000u) ? ~u : (u | 0x80000000u);
}
__device__ __forceinline__ float key2f(unsigned k) {
    unsigned u = (k & 0x80000000u) ? (k & 0x7FFFFFFFu) : ~k;
    return __uint_as_float(u);
}

struct OS { float m1, m2, s, t; };

__device__ __forceinline__ void os_merge(OS& a, const OS& b) {
    float M1 = fmaxf(a.m1, b.m1);
    float M2 = fmaxf(fminf(a.m1, b.m1), fmaxf(a.m2, b.m2));
    float sa = (a.m1 == -INFINITY) ? 0.f : __expf(a.m1 - M1);
    float sb = (b.m1 == -INFINITY) ? 0.f : __expf(b.m1 - M1);
    a.s = a.s * sa + b.s * sb;
    a.t = a.t * sa + b.t * sb;
    a.m1 = M1; a.m2 = M2;
}

// ---------------------------------------------------------------------------
// Kernel 1: one block per row, 256 threads. (streaming loop at ~6.9 TB/s cap)
// ---------------------------------------------------------------------------
__global__ void __launch_bounds__(256) row_stats_kernel(
    const float* __restrict__ lf, const int* __restrict__ tf,
    int V, float inv_logV)
{
    const int row  = blockIdx.x;
    const int tid  = threadIdx.x;
    const int lane = tid & 31;
    const float* p = lf + (size_t)row * (size_t)V;

    __shared__ OS swarp[8];
    __shared__ float s_lt;

    if (tid == 0) s_lt = __ldg(p + __ldg(tf + row));

    float m1 = -INFINITY, m2 = -INFINITY;
    float bm = -INFINITY, b2 = -INFINITY;
    float s0 = 0.f, s1 = 0.f, t0 = 0.f, t1 = 0.f;

    #define TOP2(x) { float lo_ = fminf((x), m1); m1 = fmaxf((x), m1); m2 = fmaxf(m2, lo_); }
    #define RESCALE() if (m1 > bm) { \
        float nb2_ = m1 * LOG2E; \
        float sc_  = ex2f(b2 - nb2_); \
        s0 *= sc_; s1 *= sc_; t0 *= sc_; t1 *= sc_; \
        bm = m1; b2 = nb2_; }
    #define EXP4(v) { float e_; \
        e_ = ex2f(fmaf((v).x, LOG2E, -b2)); s0 += e_; t0 = fmaf(e_, (v).x, t0); \
        e_ = ex2f(fmaf((v).y, LOG2E, -b2)); s1 += e_; t1 = fmaf(e_, (v).y, t1); \
        e_ = ex2f(fmaf((v).z, LOG2E, -b2)); s0 += e_; t0 = fmaf(e_, (v).z, t0); \
        e_ = ex2f(fmaf((v).w, LOG2E, -b2)); s1 += e_; t1 = fmaf(e_, (v).w, t1); }

    if (((V & 3) == 0) && ((((uintptr_t)p) & 15u) == 0)) {
        const int V4 = V >> 2;
        const float4* p4 = reinterpret_cast<const float4*>(p);
        const int pairs = V4 >> 9;
        int i = tid;
        if (pairs > 0) {
            float4 c0 = __ldcs(p4 + i);
            float4 c1 = __ldcs(p4 + i + 256);
            #pragma unroll 1
            for (int it = 1; it < pairs; it++) {
                int nx = i + 512;
                float4 n0 = __ldcs(p4 + nx);
                float4 n1 = __ldcs(p4 + nx + 256);
                TOP2(c0.x); TOP2(c0.y); TOP2(c0.z); TOP2(c0.w);
                TOP2(c1.x); TOP2(c1.y); TOP2(c1.z); TOP2(c1.w);
                RESCALE();
                EXP4(c0);
                EXP4(c1);
                c0 = n0; c1 = n1; i = nx;
            }
            TOP2(c0.x); TOP2(c0.y); TOP2(c0.z); TOP2(c0.w);
            TOP2(c1.x); TOP2(c1.y); TOP2(c1.z); TOP2(c1.w);
            RESCALE();
            EXP4(c0);
            EXP4(c1);
            i += 512;
        }
        for (; i < V4; i += 256) {
            float4 a = __ldcs(p4 + i);
            TOP2(a.x); TOP2(a.y); TOP2(a.z); TOP2(a.w);
            RESCALE();
            EXP4(a);
        }
    } else {
        for (int i = tid; i < V; i += 256) {
            float x = p[i];
            TOP2(x);
            RESCALE();
            float e = ex2f(fmaf(x, LOG2E, -b2));
            s0 += e; t0 = fmaf(e, x, t0);
        }
    }
    #undef TOP2
    #undef RESCALE
    #undef EXP4

    OS st;
    st.m1 = m1; st.m2 = m2; st.s = s0 + s1; st.t = t0 + t1;

    #pragma unroll
    for (int off = 16; off; off >>= 1) {
        OS o;
        o.m1 = __shfl_xor_sync(0xffffffffu, st.m1, off);
        o.m2 = __shfl_xor_sync(0xffffffffu, st.m2, off);
        o.s  = __shfl_xor_sync(0xffffffffu, st.s,  off);
        o.t  = __shfl_xor_sync(0xffffffffu, st.t,  off);
        os_merge(st, o);
    }
    if (lane == 0) swarp[tid >> 5] = st;
    __syncthreads();

    if (tid == 0) {
        #pragma unroll
        for (int w = 1; w < 8; w++) os_merge(st, swarp[w]);

        float logs = __logf(st.s);
        float logZ = st.m1 + logs;
        float ce   = logZ - s_lt;
        float ent  = logZ - st.t / st.s;
        float conf = 1.f / st.s;                    // p1, in (0, 1]
        float p2   = __expf(st.m2 - st.m1) * conf;  // p2
        float margin = conf - p2;

        g_ce[row]   = ce;
        g_part[row] = ent * inv_logV + 1.f - margin;

        atomicMax(&g_maxce_key, f2key(ce));
        unsigned long long cfx = (unsigned long long)((double)conf * 4294967296.0);
        atomicAdd(&g_sumconf_fx, cfx);

        __threadfence();   // publish before signaling dependents
        asm volatile("griddepcontrol.launch_dependents;" ::: "memory");
    }
}

// ---------------------------------------------------------------------------
// block reduction for 1024 threads (32 warps)
// ---------------------------------------------------------------------------
__device__ __forceinline__ float blk_sum32(float v, float* rbuf) {
    #pragma unroll
    for (int off = 16; off; off >>= 1)
        v += __shfl_xor_sync(0xffffffffu, v, off);
    if ((threadIdx.x & 31) == 0) rbuf[threadIdx.x >> 5] = v;
    __syncthreads();
    if (threadIdx.x < 32) {
        v = rbuf[threadIdx.x];
        #pragma unroll
        for (int off = 16; off; off >>= 1)
            v += __shfl_xor_sync(0xffffffffu, v, off);
        if (threadIdx.x == 0) rbuf[0] = v;
    }
    __syncthreads();
    float r = rbuf[0];
    __syncthreads();
    return r;
}

// warp-0 suffix-scan + winner-digit select over 256 bins. Called by tid<32.
__device__ __forceinline__ void warp0_select(
    const unsigned* hist, volatile unsigned* s_prefix, volatile int* s_rank,
    int shift)
{
    const int L = threadIdx.x;
    unsigned b[8];
    unsigned tot = 0;
    #pragma unroll
    for (int j = 0; j < 8; j++) { b[j] = hist[L * 8 + j]; tot += b[j]; }

    unsigned S = tot;
    #pragma unroll
    for (int off = 1; off < 32; off <<= 1) {
        unsigned v = __shfl_down_sync(0xffffffffu, S, off);
        if (L + off < 32) S += v;
    }
    unsigned above = S - tot;

    int r = *s_rank;
    unsigned pfx = *s_prefix;
    __syncwarp();

    unsigned run = above;
    int windig = -1; unsigned wabove = 0;
    #pragma unroll
    for (int j = 7; j >= 0; j--) {
        unsigned nrun = run + b[j];
        if ((int)nrun >= r && (int)run < r) { windig = L * 8 + j; wabove = run; }
        run = nrun;
    }
    if (windig >= 0) {
        *s_prefix = pfx | ((unsigned)windig << shift);
        *s_rank   = r - (int)wabove;
    }
}

// ---------------------------------------------------------------------------
// Kernel 2: single block, 1024 threads. PDL: ramps up concurrently with the
// row kernel, waits on the grid dependency, then runs the lean radix select.
// ---------------------------------------------------------------------------
__global__ void __launch_bounds__(1024) finalize_kernel(
    const int* __restrict__ step_ptr, float* __restrict__ out, int N)
{
    __shared__ unsigned skey[MAXN];        // 32 KB
    __shared__ float    sce[MAXN];         // 32 KB
    __shared__ unsigned hist[256];
    __shared__ float rbuf[32];
    __shared__ unsigned s_prefix;
    __shared__ int s_rank;

    const int tid  = threadIdx.x;
    const int lane = tid & 31;

    // dependency-independent setup
    if (tid < 256) hist[tid] = 0u;
    int step = *step_ptr;   // harness input, not written by row kernel

    // block until all row CTAs have signaled launch_dependents
    asm volatile("griddepcontrol.wait;" ::: "memory");

    float maxce   = key2f(g_maxce_key);
    float sumconf = (float)((double)g_sumconf_fx * (1.0 / 4294967296.0));

    if (tid == 0) {
        float progress = fminf(1.f, (float)step * (1.f / 1000.f));
        float base_rat = 1.f - progress * (1.f - 0.25f);
        float avg_conf = sumconf / (float)N;
        float ratio    = base_rat * (1.f + 0.5f * (0.5f - avg_conf) * 2.f);
        ratio = fminf(fmaxf(ratio, 0.01f), 1.f);
        int k = (int)rintf(ratio * (float)N);       // round-half-even == jnp.round
        k = min(max(k, 1), N);
        s_rank = k;
        s_prefix = 0u;
    }
    __syncthreads();

    // key build + pass-0 histogram fused
    float invm = 1.f / (maxce + 1e-6f);
    #pragma unroll 8
    for (int i = tid; i < N; i += 1024) {
        float ce = g_ce[i];
        float d  = (g_part[i] + ce * invm) * (1.f / 3.f);
        unsigned key = f2key(d);
        skey[i] = key;
        sce[i]  = ce;
        int digit = (int)(key >> 24);
        unsigned m = __match_any_sync(0xffffffffu, digit);
        int leader = __ffs(m) - 1;
        if (lane == leader)
            atomicAdd(&hist[digit], (unsigned)__popc(m));
    }
    __syncthreads();

    if (tid < 32) warp0_select(hist, &s_prefix, &s_rank, 24);
    __syncthreads();

    #pragma unroll
    for (int pass = 1; pass < 4; pass++) {
        const int shift = 24 - pass * 8;
        const unsigned himask = 0xFFFFFFFFu << (32 - pass * 8);
        if (tid < 256) hist[tid] = 0u;
        __syncthreads();
        unsigned prefix = s_prefix;

        #pragma unroll 8
        for (int i = tid; i < N; i += 1024) {
            unsigned key = skey[i];
            int digit = ((key & himask) == prefix) ? (int)((key >> shift) & 255u) : -1;
            unsigned m = __match_any_sync(0xffffffffu, digit);
            int leader = __ffs(m) - 1;
            if (lane == leader && digit >= 0)
                atomicAdd(&hist[digit], (unsigned)__popc(m));
        }
        __syncthreads();

        if (tid < 32) warp0_select(hist, &s_prefix, &s_rank, shift);
        __syncthreads();
    }
    unsigned thr_key = s_prefix;   // exact k-th largest difficulty key

    float sces = 0.f, cnt = 0.f;
    #pragma unroll 8
    for (int i = tid; i < N; i += 1024) {
        if (skey[i] >= thr_key) { sces += sce[i]; cnt += 1.f; }
    }
    sces = blk_sum32(sces, rbuf);
    cnt  = blk_sum32(cnt, rbuf);
    if (tid == 0) {
        out[0] = sces / fmaxf(cnt, 1.f);
        g_maxce_key  = 0u;          // reset for next graph replay
        g_sumconf_fx = 0ull;
    }
}

// ---------------------------------------------------------------------------
extern "C" void kernel_launch(void* const* d_in, const int* in_sizes, int n_in,
                              void* d_out, int out_size) {
    const float* lf   = (const float*)d_in[0];   // logits (B,S,V) fp32
    const int*   tf   = (const int*)d_in[1];     // targets (B,S) int32
    const int*   step = (const int*)d_in[2];     // step_count scalar int32

    int N = in_sizes[1];                 // B*S = 8192
    int V = in_sizes[0] / N;             // 32000
    if (N > MAXN) N = MAXN;

    float inv_logV = 1.f / logf((float)V);

    row_stats_kernel<<<N, 256>>>(lf, tf, V, inv_logV);

    // PDL launch: overlap finalize's launch/ramp with the row kernel's tail.
    cudaLaunchConfig_t cfg = {};
    cfg.gridDim  = dim3(1, 1, 1);
    cfg.blockDim = dim3(1024, 1, 1);
    cfg.dynamicSmemBytes = 0;
    cfg.stream = 0;
    cudaLaunchAttribute attrs[1];
    attrs[0].id = cudaLaunchAttributeProgrammaticStreamSerialization;
    attrs[0].val.programmaticStreamSerializationAllowed = 1;
    cfg.attrs = attrs;
    cfg.numAttrs = 1;
    float* outp = (float*)d_out;
    cudaError_t e = cudaLaunchKernelEx(&cfg, finalize_kernel, step, outp, N);
    if (e != cudaSuccess) {
        // fallback: plain stream-ordered launch (griddepcontrol.wait is a
        // no-op when no PDL attribute is set)
        finalize_kernel<<<1, 1024>>>(step, outp, N);
    }
}